// round 4
// baseline (speedup 1.0000x reference)
#include <cuda_runtime.h>
#include <cstdint>

// Problem constants
#define B_   8
#define CIN  256
#define COUT 256
#define H_   64
#define W_   64
#define HW   4096      // 64*64
#define G_   4
#define CPG  64        // CIN/G
#define K_   9         // 3x3
#define KD   2304      // CIN*K  (GEMM inner dim)
#define OFFC 72        // G*2*K offset channels

// Scratch (allocation-free rule: use __device__ globals)
__device__ float g_off[B_ * OFFC * HW];                    // [b][o][hw], 9.4 MB
__device__ float g_S[(size_t)B_ * KD * HW];                // [b][cin*9+k][hw], 302 MB

// ---------------------------------------------------------------------------
// Kernel 1: offset = w_offset[72x4] @ shape[b,4,hw]
// ---------------------------------------------------------------------------
__global__ void offset_kernel(const float* __restrict__ shape,
                              const float* __restrict__ wo) {
    int idx = blockIdx.x * blockDim.x + threadIdx.x;
    if (idx >= B_ * OFFC * HW) return;
    int hw = idx & (HW - 1);
    int o  = (idx >> 12) % OFFC;
    int b  = idx / (OFFC * HW);
    const float* sp = shape + (size_t)b * 4 * HW + hw;
    float acc = wo[o * 4 + 0] * sp[0]
              + wo[o * 4 + 1] * sp[HW]
              + wo[o * 4 + 2] * sp[2 * HW]
              + wo[o * 4 + 3] * sp[3 * HW];
    g_off[idx] = acc;
}

// ---------------------------------------------------------------------------
// Kernel 2: bilinear gather. One thread per (b,g,k,hw); loops 64 channels.
// Computes weights/indices once, reuses for all channels of the group.
// ---------------------------------------------------------------------------
__global__ void gather_kernel(const float* __restrict__ x) {
    int idx = blockIdx.x * blockDim.x + threadIdx.x;
    if (idx >= B_ * G_ * K_ * HW) return;
    int hw = idx & (HW - 1);
    int k  = (idx >> 12) % K_;
    int bg = idx / (K_ * HW);
    int g  = bg & 3;
    int b  = bg >> 2;

    // off channel o = (g*9+k)*2 + {0,1}; bg*9+k = b*36 + g*9 + k
    float dy = g_off[(size_t)((bg * K_ + k) * 2 + 0) * HW + hw];
    float dx = g_off[(size_t)((bg * K_ + k) * 2 + 1) * HW + hw];

    int h = hw >> 6, w = hw & 63;
    float py = (float)(h + (k / 3) - 1) + dy;
    float px = (float)(w + (k % 3) - 1) + dx;

    float y0f = floorf(py), x0f = floorf(px);
    int y0 = (int)y0f, x0 = (int)x0f;
    int y1 = y0 + 1,   x1 = x0 + 1;
    float ly = py - y0f, lx = px - x0f;
    float w00 = (1.f - ly) * (1.f - lx);
    float w01 = (1.f - ly) * lx;
    float w10 = ly * (1.f - lx);
    float w11 = ly * lx;

    bool vy0 = (y0 >= 0) & (y0 < H_);
    bool vy1 = (y1 >= 0) & (y1 < H_);
    bool vx0 = (x0 >= 0) & (x0 < W_);
    bool vx1 = (x1 >= 0) & (x1 < W_);
    if (!(vy0 & vx0)) w00 = 0.f;
    if (!(vy0 & vx1)) w01 = 0.f;
    if (!(vy1 & vx0)) w10 = 0.f;
    if (!(vy1 & vx1)) w11 = 0.f;

    int cy0 = min(max(y0, 0), H_ - 1), cy1 = min(max(y1, 0), H_ - 1);
    int cx0 = min(max(x0, 0), W_ - 1), cx1 = min(max(x1, 0), W_ - 1);
    int i00 = cy0 * W_ + cx0, i01 = cy0 * W_ + cx1;
    int i10 = cy1 * W_ + cx0, i11 = cy1 * W_ + cx1;

    const float* xp = x + (size_t)(b * CIN + g * CPG) * HW;
    float* sp = g_S + (size_t)b * KD * HW + (size_t)((g * CPG) * K_ + k) * HW + hw;

#pragma unroll 4
    for (int c = 0; c < CPG; c++) {
        const float* xc = xp + (size_t)c * HW;
        float v = w00 * __ldg(&xc[i00]) + w01 * __ldg(&xc[i01])
                + w10 * __ldg(&xc[i10]) + w11 * __ldg(&xc[i11]);
        sp[(size_t)c * K_ * HW] = v;
    }
}

// ---------------------------------------------------------------------------
// Kernel 3: batched SGEMM  C[b] = relu( A[256x2304] @ S[b][2304x4096] )
// A = w_deform flattened (j = cin*9+k is exactly its inner layout).
// Tiles: BM=128, BN=128, BK=16, 256 threads, 8x8 per-thread micro-tile.
// All dims divide tiles exactly -> no bounds checks.
// ---------------------------------------------------------------------------
#define BM 128
#define BN 128
#define BK 16
__global__ __launch_bounds__(256, 2)
void gemm_kernel(const float* __restrict__ A, float* __restrict__ C) {
    int b = blockIdx.z;
    const float* Bp = g_S + (size_t)b * KD * HW;
    float* Cp = C + (size_t)b * COUT * HW;
    int tile_n = blockIdx.x * BN;
    int tile_m = blockIdx.y * BM;

    __shared__ float As[BK][BM];   // transposed A tile
    __shared__ float Bs[BK][BN];

    int tid  = threadIdx.x;
    int tcol = tid & 15;   // n direction
    int trow = tid >> 4;   // m direction

    // A-tile load mapping: 128 rows x 16 k = 512 float4, 2 per thread
    int a_row = tid >> 2;         // 0..63
    int a_k4  = (tid & 3) * 4;    // 0,4,8,12
    // B-tile load mapping: 16 rows x 128 n = 512 float4, 2 per thread
    int b_row = tid >> 5;         // 0..7
    int b_col = (tid & 31) * 4;

    float acc[8][8];
#pragma unroll
    for (int i = 0; i < 8; i++)
#pragma unroll
        for (int j = 0; j < 8; j++) acc[i][j] = 0.f;

    for (int kt = 0; kt < KD; kt += BK) {
        float4 a0 = *(const float4*)(A + (size_t)(tile_m + a_row) * KD + kt + a_k4);
        float4 a1 = *(const float4*)(A + (size_t)(tile_m + a_row + 64) * KD + kt + a_k4);
        As[a_k4 + 0][a_row] = a0.x;
        As[a_k4 + 1][a_row] = a0.y;
        As[a_k4 + 2][a_row] = a0.z;
        As[a_k4 + 3][a_row] = a0.w;
        As[a_k4 + 0][a_row + 64] = a1.x;
        As[a_k4 + 1][a_row + 64] = a1.y;
        As[a_k4 + 2][a_row + 64] = a1.z;
        As[a_k4 + 3][a_row + 64] = a1.w;

        *(float4*)&Bs[b_row][b_col] =
            *(const float4*)(Bp + (size_t)(kt + b_row) * HW + tile_n + b_col);
        *(float4*)&Bs[b_row + 8][b_col] =
            *(const float4*)(Bp + (size_t)(kt + b_row + 8) * HW + tile_n + b_col);

        __syncthreads();

#pragma unroll
        for (int kk = 0; kk < BK; kk++) {
            float4 av0 = *(const float4*)&As[kk][trow * 8];
            float4 av1 = *(const float4*)&As[kk][trow * 8 + 4];
            float4 bv0 = *(const float4*)&Bs[kk][tcol * 8];
            float4 bv1 = *(const float4*)&Bs[kk][tcol * 8 + 4];
            float ar[8] = {av0.x, av0.y, av0.z, av0.w, av1.x, av1.y, av1.z, av1.w};
            float br[8] = {bv0.x, bv0.y, bv0.z, bv0.w, bv1.x, bv1.y, bv1.z, bv1.w};
#pragma unroll
            for (int i = 0; i < 8; i++)
#pragma unroll
                for (int j = 0; j < 8; j++)
                    acc[i][j] = fmaf(ar[i], br[j], acc[i][j]);
        }
        __syncthreads();
    }

    // Store with ReLU, vectorized
#pragma unroll
    for (int i = 0; i < 8; i++) {
        int row = tile_m + trow * 8 + i;
        float* cp = Cp + (size_t)row * HW + tile_n + tcol * 8;
        float4 v0, v1;
        v0.x = fmaxf(acc[i][0], 0.f); v0.y = fmaxf(acc[i][1], 0.f);
        v0.z = fmaxf(acc[i][2], 0.f); v0.w = fmaxf(acc[i][3], 0.f);
        v1.x = fmaxf(acc[i][4], 0.f); v1.y = fmaxf(acc[i][5], 0.f);
        v1.z = fmaxf(acc[i][6], 0.f); v1.w = fmaxf(acc[i][7], 0.f);
        *(float4*)cp = v0;
        *(float4*)(cp + 4) = v1;
    }
}

// ---------------------------------------------------------------------------
extern "C" void kernel_launch(void* const* d_in, const int* in_sizes, int n_in,
                              void* d_out, int out_size) {
    const float* x        = (const float*)d_in[0];   // [8,256,64,64]
    const float* shape    = (const float*)d_in[1];   // [8,4,64,64]
    const float* w_offset = (const float*)d_in[2];   // [72,4]
    const float* w_deform = (const float*)d_in[3];   // [256,256,3,3]
    float* out = (float*)d_out;                      // [8,256,64,64]

    {
        int n = B_ * OFFC * HW;
        offset_kernel<<<(n + 255) / 256, 256>>>(shape, w_offset);
    }
    {
        int n = B_ * G_ * K_ * HW;
        gather_kernel<<<(n + 255) / 256, 256>>>(x);
    }
    {
        dim3 grid(HW / BN, COUT / BM, B_);
        gemm_kernel<<<grid, 256>>>(w_deform, out);
    }
}

// round 7
// speedup vs baseline: 2.2675x; 2.2675x over previous
#include <cuda_runtime.h>
#include <cuda_bf16.h>
#include <cstdint>

// Problem constants
#define B_   8
#define CIN  256
#define COUT 256
#define H_   64
#define W_   64
#define HW   4096      // 64*64
#define G_   4
#define CPG  64        // CIN/G
#define K_   9         // 3x3
#define KD   2304      // CIN*K  (GEMM inner dim)
#define OFFC 72        // G*2*K offset channels

// GEMM tiling
#define BM    128
#define BN    128
#define BK    32
#define NCHK  (KD / BK)      // 72 k-chunks

// Scratch (__device__ globals per allocation rules)
__device__ float g_off[B_ * OFFC * HW];                                  // 9.4 MB
__device__ __align__(16) __nv_bfloat16 g_Sh[(size_t)B_ * KD * HW];       // 151 MB
__device__ __align__(16) __nv_bfloat16 g_Sl[(size_t)B_ * KD * HW];       // 151 MB
__device__ __align__(16) __nv_bfloat16 g_Ah[COUT * KD];
__device__ __align__(16) __nv_bfloat16 g_Al[COUT * KD];

// ---------------------------------------------------------------------------
// PTX helpers
// ---------------------------------------------------------------------------
__device__ __forceinline__ uint32_t smem_u32(const void* p) {
    uint32_t a;
    asm("{ .reg .u64 t; cvta.to.shared.u64 t, %1; cvt.u32.u64 %0, t; }"
        : "=r"(a) : "l"(p));
    return a;
}

__device__ __forceinline__ void cp16(uint32_t s, const void* g) {
    asm volatile("cp.async.cg.shared.global [%0], [%1], 16;"
                 :: "r"(s), "l"((unsigned long long)__cvta_generic_to_global(g)) : "memory");
}

__device__ __forceinline__ void ldsm4(uint32_t* r, uint32_t a) {
    asm volatile("ldmatrix.sync.aligned.m8n8.x4.shared.b16 {%0,%1,%2,%3}, [%4];"
                 : "=r"(r[0]), "=r"(r[1]), "=r"(r[2]), "=r"(r[3]) : "r"(a));
}

__device__ __forceinline__ void ldsm4t(uint32_t* r, uint32_t a) {
    asm volatile("ldmatrix.sync.aligned.m8n8.x4.trans.shared.b16 {%0,%1,%2,%3}, [%4];"
                 : "=r"(r[0]), "=r"(r[1]), "=r"(r[2]), "=r"(r[3]) : "r"(a));
}

__device__ __forceinline__ void mma16816(float* c, const uint32_t* a, const uint32_t* b) {
    asm volatile("mma.sync.aligned.m16n8k16.row.col.f32.bf16.bf16.f32 "
                 "{%0,%1,%2,%3}, {%4,%5,%6,%7}, {%8,%9}, {%0,%1,%2,%3};"
                 : "+f"(c[0]), "+f"(c[1]), "+f"(c[2]), "+f"(c[3])
                 : "r"(a[0]), "r"(a[1]), "r"(a[2]), "r"(a[3]), "r"(b[0]), "r"(b[1]));
}

// ---------------------------------------------------------------------------
// Kernel 1: offset = w_offset[72x4] @ shape[b,4,hw]
// ---------------------------------------------------------------------------
__global__ void offset_kernel(const float* __restrict__ shape,
                              const float* __restrict__ wo) {
    int idx = blockIdx.x * blockDim.x + threadIdx.x;
    if (idx >= B_ * OFFC * HW) return;
    int hw = idx & (HW - 1);
    int o  = (idx >> 12) % OFFC;
    int b  = idx / (OFFC * HW);
    const float* sp = shape + (size_t)b * 4 * HW + hw;
    float acc = wo[o * 4 + 0] * sp[0]
              + wo[o * 4 + 1] * sp[HW]
              + wo[o * 4 + 2] * sp[2 * HW]
              + wo[o * 4 + 3] * sp[3 * HW];
    g_off[idx] = acc;
}

// ---------------------------------------------------------------------------
// Kernel 1b: split weights into bf16 hi/lo
// ---------------------------------------------------------------------------
__global__ void wconv_kernel(const float* __restrict__ w) {
    int idx = blockIdx.x * blockDim.x + threadIdx.x;
    if (idx >= COUT * KD) return;
    float v = w[idx];
    __nv_bfloat16 hi = __float2bfloat16(v);
    __nv_bfloat16 lo = __float2bfloat16(v - __bfloat162float(hi));
    g_Ah[idx] = hi;
    g_Al[idx] = lo;
}

// ---------------------------------------------------------------------------
// Kernel 2: bilinear gather -> split-bf16 S_hi/S_lo, layout [b][cin*9+k][hw]
// ---------------------------------------------------------------------------
__global__ void gather_kernel(const float* __restrict__ x) {
    int idx = blockIdx.x * blockDim.x + threadIdx.x;
    if (idx >= B_ * G_ * K_ * HW) return;
    int hw = idx & (HW - 1);
    int k  = (idx >> 12) % K_;
    int bg = idx / (K_ * HW);
    int g  = bg & 3;
    int b  = bg >> 2;

    float dy = g_off[(size_t)((bg * K_ + k) * 2 + 0) * HW + hw];
    float dx = g_off[(size_t)((bg * K_ + k) * 2 + 1) * HW + hw];

    int h = hw >> 6, w = hw & 63;
    float py = (float)(h + (k / 3) - 1) + dy;
    float px = (float)(w + (k % 3) - 1) + dx;

    float y0f = floorf(py), x0f = floorf(px);
    int y0 = (int)y0f, x0 = (int)x0f;
    int y1 = y0 + 1,   x1 = x0 + 1;
    float ly = py - y0f, lx = px - x0f;
    float w00 = (1.f - ly) * (1.f - lx);
    float w01 = (1.f - ly) * lx;
    float w10 = ly * (1.f - lx);
    float w11 = ly * lx;

    bool vy0 = (y0 >= 0) & (y0 < H_);
    bool vy1 = (y1 >= 0) & (y1 < H_);
    bool vx0 = (x0 >= 0) & (x0 < W_);
    bool vx1 = (x1 >= 0) & (x1 < W_);
    if (!(vy0 & vx0)) w00 = 0.f;
    if (!(vy0 & vx1)) w01 = 0.f;
    if (!(vy1 & vx0)) w10 = 0.f;
    if (!(vy1 & vx1)) w11 = 0.f;

    int cy0 = min(max(y0, 0), H_ - 1), cy1 = min(max(y1, 0), H_ - 1);
    int cx0 = min(max(x0, 0), W_ - 1), cx1 = min(max(x1, 0), W_ - 1);
    int i00 = cy0 * W_ + cx0, i01 = cy0 * W_ + cx1;
    int i10 = cy1 * W_ + cx0, i11 = cy1 * W_ + cx1;

    const float* xp = x + (size_t)(b * CIN + g * CPG) * HW;
    size_t sbase = (size_t)b * KD * HW + (size_t)((g * CPG) * K_ + k) * HW + hw;

#pragma unroll 4
    for (int c = 0; c < CPG; c++) {
        const float* xc = xp + (size_t)c * HW;
        float v = w00 * __ldg(&xc[i00]) + w01 * __ldg(&xc[i01])
                + w10 * __ldg(&xc[i10]) + w11 * __ldg(&xc[i11]);
        __nv_bfloat16 hi = __float2bfloat16(v);
        __nv_bfloat16 lo = __float2bfloat16(v - __bfloat162float(hi));
        size_t si = sbase + (size_t)c * (K_ * HW);
        g_Sh[si] = hi;
        g_Sl[si] = lo;
    }
}

// ---------------------------------------------------------------------------
// Kernel 3: split-bf16 GEMM via mma.sync (HMMA)
//   C[b] = relu( A[256x2304] @ S[b][2304x4096] )
//   CTA tile 128x128, BK=32, 8 warps each 64x32 (warp grid 2m x 4n).
//   D += Ah*Bh + Ah*Bl + Al*Bh   (fp32 accum in registers)
//
// SMEM per stage:
//   A tiles [128 m][32 k] bf16, row pitch 80B  -> hi @0, lo @10240
//   B tiles [32 k][128 n] bf16, row pitch 272B -> hi @20480, lo @29184
//   (odd pitches -> conflict-free ldmatrix and cp.async stores)
// ---------------------------------------------------------------------------
#define APITCH 80
#define BPITCH 272
#define OFF_AL 10240
#define OFF_BH 20480
#define OFF_BL 29184
#define STG_BYTES 37888
#define DYN_SMEM (2 * STG_BYTES)

__device__ __forceinline__ void load_chunk(int chunk, int stage, int tid,
                                           int mt, int nt, int b, uint32_t sb) {
    int kt = chunk * BK;
    uint32_t st = sb + stage * STG_BYTES;
    const __nv_bfloat16* Ah = g_Ah + (size_t)(mt * BM) * KD + kt;
    const __nv_bfloat16* Al = g_Al + (size_t)(mt * BM) * KD + kt;
    const __nv_bfloat16* Sh = g_Sh + ((size_t)b * KD + kt) * HW + nt * BN;
    const __nv_bfloat16* Sl = g_Sl + ((size_t)b * KD + kt) * HW + nt * BN;
#pragma unroll
    for (int j = 0; j < 2; j++) {
        int u = tid + j * 256;                  // 0..511
        // A: 128 rows x 4 chunks (16B) each
        int ar = u >> 2, ac = u & 3;
        uint32_t da = st + ar * APITCH + ac * 16;
        cp16(da,          Ah + (size_t)ar * KD + ac * 8);
        cp16(da + OFF_AL, Al + (size_t)ar * KD + ac * 8);
        // B: 32 rows x 16 chunks each
        int br = u >> 4, bc = u & 15;
        uint32_t db = st + br * BPITCH + bc * 16;
        cp16(db + OFF_BH, Sh + (size_t)br * HW + bc * 8);
        cp16(db + OFF_BL, Sl + (size_t)br * HW + bc * 8);
    }
}

__global__ __launch_bounds__(256)
void hmma_gemm_kernel(float* __restrict__ out) {
    extern __shared__ char smem[];
    uint32_t sb = smem_u32(smem);
    int tid = threadIdx.x, wid = tid >> 5, lid = tid & 31;
    int nt = blockIdx.x, mt = blockIdx.y, b = blockIdx.z;
    int warp_m = wid & 1;       // 0..1  (64 rows each)
    int warp_n = wid >> 1;      // 0..3  (32 cols each)

    float acc[4][4][4];
#pragma unroll
    for (int i = 0; i < 4; i++)
#pragma unroll
        for (int j = 0; j < 4; j++)
#pragma unroll
            for (int r = 0; r < 4; r++) acc[i][j][r] = 0.f;

    // ldmatrix lane addressing (relative to stage base):
    //  A tile: lanes 0-15 rows (l&15), lanes 16-31 same rows +16B (k8..15)
    uint32_t a_lane = (uint32_t)((warp_m * 64 + (lid & 15)) * APITCH + (lid >> 4) * 16);
    //  B tile: rows = k (l&15), +16B for n8..15 block; + warp_n*64B
    uint32_t b_lane = (uint32_t)((lid & 15) * BPITCH + (lid >> 4) * 16 + warp_n * 64);

    // Prologue
    load_chunk(0, 0, tid, mt, nt, b, sb);
    asm volatile("cp.async.commit_group;" ::: "memory");

    for (int i = 0; i < NCHK; i++) {
        int p = i & 1;
        if (i + 1 < NCHK) {
            load_chunk(i + 1, p ^ 1, tid, mt, nt, b, sb);
            asm volatile("cp.async.commit_group;" ::: "memory");
            asm volatile("cp.async.wait_group 1;" ::: "memory");
        } else {
            asm volatile("cp.async.wait_group 0;" ::: "memory");
        }
        __syncthreads();

        uint32_t st = sb + p * STG_BYTES;
        uint32_t abase = st + a_lane;
        uint32_t bbase = st + b_lane;

#pragma unroll
        for (int k16 = 0; k16 < 2; k16++) {
            uint32_t ah[4][4], al[4][4], bh[4][2], bl[4][2];
#pragma unroll
            for (int fm = 0; fm < 4; fm++) {
                ldsm4(ah[fm], abase + fm * (16 * APITCH) + k16 * 32);
                ldsm4(al[fm], abase + OFF_AL + fm * (16 * APITCH) + k16 * 32);
            }
#pragma unroll
            for (int j = 0; j < 2; j++) {
                uint32_t r[4];
                ldsm4t(r, bbase + OFF_BH + k16 * (16 * BPITCH) + j * 32);
                bh[2 * j][0] = r[0]; bh[2 * j][1] = r[1];
                bh[2 * j + 1][0] = r[2]; bh[2 * j + 1][1] = r[3];
                ldsm4t(r, bbase + OFF_BL + k16 * (16 * BPITCH) + j * 32);
                bl[2 * j][0] = r[0]; bl[2 * j][1] = r[1];
                bl[2 * j + 1][0] = r[2]; bl[2 * j + 1][1] = r[3];
            }
            // term 1: Ah*Bh
#pragma unroll
            for (int fm = 0; fm < 4; fm++)
#pragma unroll
                for (int fn = 0; fn < 4; fn++)
                    mma16816(acc[fm][fn], ah[fm], bh[fn]);
            // term 2: Ah*Bl
#pragma unroll
            for (int fm = 0; fm < 4; fm++)
#pragma unroll
                for (int fn = 0; fn < 4; fn++)
                    mma16816(acc[fm][fn], ah[fm], bl[fn]);
            // term 3: Al*Bh
#pragma unroll
            for (int fm = 0; fm < 4; fm++)
#pragma unroll
                for (int fn = 0; fn < 4; fn++)
                    mma16816(acc[fm][fn], al[fm], bh[fn]);
        }
        __syncthreads();
    }

    // Epilogue: ReLU + store. m16n8 accum: thread t -> rows t/4, t/4+8; cols (t%4)*2, +1
    int rbase = mt * BM + warp_m * 64 + (lid >> 2);
    int cbase = nt * BN + warp_n * 32 + (lid & 3) * 2;
    float* op = out + (size_t)b * COUT * HW;
#pragma unroll
    for (int fm = 0; fm < 4; fm++) {
#pragma unroll
        for (int fn = 0; fn < 4; fn++) {
            int rr = rbase + fm * 16;
            int cc = cbase + fn * 8;
            float2 v0, v1;
            v0.x = fmaxf(acc[fm][fn][0], 0.f);
            v0.y = fmaxf(acc[fm][fn][1], 0.f);
            v1.x = fmaxf(acc[fm][fn][2], 0.f);
            v1.y = fmaxf(acc[fm][fn][3], 0.f);
            *(float2*)(op + (size_t)rr * HW + cc) = v0;
            *(float2*)(op + (size_t)(rr + 8) * HW + cc) = v1;
        }
    }
}

// ---------------------------------------------------------------------------
extern "C" void kernel_launch(void* const* d_in, const int* in_sizes, int n_in,
                              void* d_out, int out_size) {
    const float* x        = (const float*)d_in[0];   // [8,256,64,64]
    const float* shape    = (const float*)d_in[1];   // [8,4,64,64]
    const float* w_offset = (const float*)d_in[2];   // [72,4]
    const float* w_deform = (const float*)d_in[3];   // [256,256,3,3]
    float* out = (float*)d_out;                      // [8,256,64,64]

    cudaFuncSetAttribute(hmma_gemm_kernel,
                         cudaFuncAttributeMaxDynamicSharedMemorySize, DYN_SMEM);

    {
        int n = B_ * OFFC * HW;
        offset_kernel<<<(n + 255) / 256, 256>>>(shape, w_offset);
    }
    {
        int n = COUT * KD;
        wconv_kernel<<<(n + 255) / 256, 256>>>(w_deform);
    }
    {
        int n = B_ * G_ * K_ * HW;
        gather_kernel<<<(n + 255) / 256, 256>>>(x);
    }
    {
        dim3 grid(HW / BN, COUT / BM, B_);
        hmma_gemm_kernel<<<grid, 256, DYN_SMEM>>>(out);
    }
}